// round 15
// baseline (speedup 1.0000x reference)
#include <cuda_runtime.h>
#include <cstdint>

#define B_    512
#define HW_   128
#define C1_   32
#define C2_   64

// Padded intermediate h: [512][32][66][68], zero border. Valid data [1..64][1..64].
#define HP_R   66
#define HP_C   68
#define HP_CH  (HP_R * HP_C)          // 4488
__device__ float g_h[(size_t)B_ * C1_ * HP_CH];   // ~294 MB

// Pre-packed conv2 weights: [cc][oc][cil][ky][4], pre-scaled by BN scale.
__device__ float g_w2p[8 * 3072];
// Per-image partial sums from conv2 blocks: [b][8]  (2 x-tiles * 4 y-tiles)
__device__ float g_part[B_ * 8];

// ---- cp.async helpers -----------------------------------------------------
__device__ __forceinline__ uint32_t sptr(const void* p) {
    return (uint32_t)__cvta_generic_to_shared(p);
}
__device__ __forceinline__ void cpa16(uint32_t dst, const void* src) {
    asm volatile("cp.async.cg.shared.global [%0], [%1], 16;" :: "r"(dst), "l"(src));
}
__device__ __forceinline__ void cpa4(uint32_t dst, const void* src) {
    asm volatile("cp.async.ca.shared.global [%0], [%1], 4;" :: "r"(dst), "l"(src));
}
__device__ __forceinline__ void cpa_commit() {
    asm volatile("cp.async.commit_group;" ::: "memory");
}
template <int N>
__device__ __forceinline__ void cpa_wait() {
    asm volatile("cp.async.wait_group %0;" :: "n"(N) : "memory");
}

// ---------------------------------------------------------------------------
// Kernel 0: pre-pack conv2 weights (18432 items)
// ---------------------------------------------------------------------------
__global__ void conv2_prep(const float* __restrict__ w2,
                           const float* __restrict__ g2,
                           const float* __restrict__ v2)
{
    int i = blockIdx.x * 256 + threadIdx.x;
    if (i >= 8 * C2_ * 36) return;
    int cc  = i / (C2_ * 36);
    int rem = i % (C2_ * 36);
    int oc  = rem / 36;
    int k2  = rem % 36;
    int cil = k2 / 9, k = k2 % 9;
    int ky = k / 3, kx = k % 3;
    float inv = g2[oc] * rsqrtf(v2[oc] + 1e-5f);
    g_w2p[cc * 3072 + oc * 48 + cil * 12 + ky * 4 + kx] =
        w2[oc * (C1_ * 9) + (cc * 4 + cil) * 9 + k] * inv;
}

// ---------------------------------------------------------------------------
// Kernel 1: Conv(3->32, k3, s1, p1) + BN + ReLU + MaxPool2  (R12 form)
// Grid (2, 4, 512), 256 thr. Two horizontal pooled pixels per thread.
// ---------------------------------------------------------------------------
__global__ void __launch_bounds__(256) conv1_fused(
    const float* __restrict__ crops,
    const float* __restrict__ w1, const float* __restrict__ b1,
    const float* __restrict__ g1, const float* __restrict__ be1,
    const float* __restrict__ m1, const float* __restrict__ v1)
{
    __shared__ float s_in[3][34][68];
    __shared__ __align__(16) float s_w[C1_ * 36];
    __shared__ float s_bias[C1_];

    const int b   = blockIdx.z;
    const int cx0 = blockIdx.x * 64;
    const int cy0 = blockIdx.y * 32;
    const int t   = threadIdx.x;

    if (t < C1_) {
        float inv = g1[t] * rsqrtf(v1[t] + 1e-5f);
        s_bias[t] = be1[t] + (b1[t] - m1[t]) * inv;
    }
    for (int i = t; i < C1_ * 27; i += 256) {
        int oc = i / 27, k = i % 27;
        int ci = k / 9, ky = (k % 9) / 3, kx = k % 3;
        float inv = g1[oc] * rsqrtf(v1[oc] + 1e-5f);
        s_w[oc * 36 + ci * 12 + ky * 4 + kx] = w1[i] * inv;
    }

    const float* cb = crops + (size_t)b * 3 * HW_ * HW_;
    for (int i = t; i < 3 * 34 * 66; i += 256) {
        int ci = i / (34 * 66);
        int rem = i % (34 * 66);
        int r = rem / 66, c = rem % 66;
        int gr = cy0 - 1 + r, gc = cx0 - 1 + c;
        float v = 0.f;
        if (gr >= 0 && gr < HW_ && gc >= 0 && gc < HW_)
            v = cb[ci * HW_ * HW_ + gr * HW_ + gc];
        s_in[ci][r][c] = v;
    }
    __syncthreads();

    const int q  = t & 15;          // pooled col-pair index (covers 2q, 2q+1)
    const int py = t >> 4;          // pooled row in tile (0..15)

    float p[3][4][6];
#pragma unroll
    for (int ci = 0; ci < 3; ci++)
#pragma unroll
        for (int r = 0; r < 4; r++) {
            const float* row = &s_in[ci][2 * py + r][4 * q];
            float4 v4 = *(const float4*)row;
            float2 v2 = *(const float2*)(row + 4);
            p[ci][r][0] = v4.x; p[ci][r][1] = v4.y; p[ci][r][2] = v4.z;
            p[ci][r][3] = v4.w; p[ci][r][4] = v2.x; p[ci][r][5] = v2.y;
        }

    const int oy = blockIdx.y * 16 + py;
    const int ox = blockIdx.x * 32 + 2 * q;
    float* hp = g_h + (size_t)b * C1_ * HP_CH + (oy + 1) * HP_C + (ox + 1);
    const float* wp = s_w;

    for (int oc = 0; oc < C1_; oc++, hp += HP_CH, wp += 36) {
        float a00 = 0.f, a01 = 0.f, a10 = 0.f, a11 = 0.f;
        float c00 = 0.f, c01 = 0.f, c10 = 0.f, c11 = 0.f;
        const float4* w4 = (const float4*)wp;
#pragma unroll
        for (int ci = 0; ci < 3; ci++)
#pragma unroll
            for (int ky = 0; ky < 3; ky++) {
                float4 w = w4[ci * 3 + ky];
                const float* r0 = p[ci][ky];
                const float* r1 = p[ci][ky + 1];
                a00 = fmaf(r0[0], w.x, a00);  a01 = fmaf(r0[1], w.x, a01);
                a10 = fmaf(r1[0], w.x, a10);  a11 = fmaf(r1[1], w.x, a11);
                c00 = fmaf(r0[2], w.x, c00);  c01 = fmaf(r0[3], w.x, c01);
                c10 = fmaf(r1[2], w.x, c10);  c11 = fmaf(r1[3], w.x, c11);
                a00 = fmaf(r0[1], w.y, a00);  a01 = fmaf(r0[2], w.y, a01);
                a10 = fmaf(r1[1], w.y, a10);  a11 = fmaf(r1[2], w.y, a11);
                c00 = fmaf(r0[3], w.y, c00);  c01 = fmaf(r0[4], w.y, c01);
                c10 = fmaf(r1[3], w.y, c10);  c11 = fmaf(r1[4], w.y, c11);
                a00 = fmaf(r0[2], w.z, a00);  a01 = fmaf(r0[3], w.z, a01);
                a10 = fmaf(r1[2], w.z, a10);  a11 = fmaf(r1[3], w.z, a11);
                c00 = fmaf(r0[4], w.z, c00);  c01 = fmaf(r0[5], w.z, c01);
                c10 = fmaf(r1[4], w.z, c10);  c11 = fmaf(r1[5], w.z, c11);
            }
        float bi = s_bias[oc];
        float mA = fmaxf(fmaxf(a00, a01), fmaxf(a10, a11)) + bi;
        float mB = fmaxf(fmaxf(c00, c01), fmaxf(c10, c11)) + bi;
        hp[0] = fmaxf(mA, 0.f);
        hp[1] = fmaxf(mB, 0.f);
    }
}

// ---------------------------------------------------------------------------
// Kernel 2: Conv(32->64, s2) + BN + Sigmoid + MaxPool2, cp.async pipeline.
// SPATIAL split: grid (2, 4, 512), block = 8x4 pooled tile, 256 thr =
// 32 pixels x 8 groups of 8 oc. acc = 32 regs -> 3 CTAs/SM (24 warps).
// Stage (floats): in [4][17][36] = 2448 | w 3072 -> STG2_F = 5520 (22.1 KB).
// ---------------------------------------------------------------------------
#define STG2_F       5520
#define STG2_W_OFF   2448
#define BI2_OFF      (2 * STG2_F)          // 11040
#define RED2_OFF     (BI2_OFF + 64)        // 11104
#define CONV2_SMEM_BYTES  ((2 * STG2_F + 64 + 8) * 4)

__global__ void __launch_bounds__(256, 3) conv2_fused(
    const float* __restrict__ b2, const float* __restrict__ g2,
    const float* __restrict__ be2, const float* __restrict__ m2,
    const float* __restrict__ v2,
    float* __restrict__ feat)
{
    extern __shared__ __align__(16) float sm[];

    const int b   = blockIdx.z;
    const int bx  = blockIdx.x;            // 0..1 : pooled cols 8*bx..
    const int byy = blockIdx.y;            // 0..3 : pooled rows 4*byy..
    const int t   = threadIdx.x;

    if (t < C2_) {
        float inv = g2[t] * rsqrtf(v2[t] + 1e-5f);
        sm[BI2_OFF + t] = be2[t] + (b2[t] - m2[t]) * inv;
    }

    // padded base: input rows 16*byy.., cols 32*bx.. (border shift included)
    const float* hp = g_h + (size_t)b * C1_ * HP_CH + (16 * byy) * HP_C + (32 * bx);
    const uint32_t sm_u32 = sptr(sm);

    auto issue = [&](int cc, int p) {
        const uint32_t base = sm_u32 + (uint32_t)(p * STG2_F) * 4u;
        // inputs: 4 ch x 17 rows x (8 float4 + 1 float) = 612 items
        for (int i = t; i < 612; i += 256) {
            int ch  = i / 153;
            int rem = i - ch * 153;
            int r   = rem / 9;
            int s   = rem - r * 9;
            const float* src = hp + (cc * 4 + ch) * HP_CH + r * HP_C;
            uint32_t dst = base + (uint32_t)((ch * 17 + r) * 36) * 4u;
            if (s < 8) cpa16(dst + 16u * s, src + 4 * s);
            else       cpa4(dst + 128u, src + 32);
        }
        // weights: full 64 oc chunk, 768 x 16B
        const float4* ws = (const float4*)(g_w2p + cc * 3072);
        const uint32_t wb = base + STG2_W_OFF * 4u;
        for (int i = t; i < 768; i += 256)
            cpa16(wb + 16u * i, ws + i);
        cpa_commit();
    };

    const int pix = t & 31, grp = t >> 5;      // grp 0..7 -> 8 oc each
    const int px = pix & 7, py = pix >> 3;     // 8x4 pooled tile

    float acc[8][2][2];
#pragma unroll
    for (int i = 0; i < 8; i++) {
        acc[i][0][0] = 0.f; acc[i][0][1] = 0.f;
        acc[i][1][0] = 0.f; acc[i][1][1] = 0.f;
    }

    issue(0, 0);

    for (int cc = 0; cc < 8; cc++) {
        const int cur = cc & 1;
        if (cc < 7) { issue(cc + 1, cur ^ 1); cpa_wait<1>(); }
        else        { cpa_wait<0>(); }
        __syncthreads();

        const float* sin = sm + cur * STG2_F;
        const float* sw  = sin + STG2_W_OFF;

#pragma unroll
        for (int cil = 0; cil < 4; cil++) {
            const float* row = sin + (cil * 17 + 4 * py) * 36 + 4 * px;
            float p[5][5];
#pragma unroll
            for (int r = 0; r < 5; r++) {
                float4 v4 = *(const float4*)(row + r * 36);
                p[r][0] = v4.x; p[r][1] = v4.y; p[r][2] = v4.z; p[r][3] = v4.w;
                p[r][4] = row[r * 36 + 4];
            }

#pragma unroll
            for (int oc = 0; oc < 8; oc++) {
                const float4* w4 = (const float4*)(sw + (grp * 8 + oc) * 48 + cil * 12);
#pragma unroll
                for (int ky = 0; ky < 3; ky++) {
                    float4 w = w4[ky];
                    acc[oc][0][0] = fmaf(p[ky    ][0], w.x, acc[oc][0][0]);
                    acc[oc][0][1] = fmaf(p[ky    ][2], w.x, acc[oc][0][1]);
                    acc[oc][1][0] = fmaf(p[ky + 2][0], w.x, acc[oc][1][0]);
                    acc[oc][1][1] = fmaf(p[ky + 2][2], w.x, acc[oc][1][1]);
                    acc[oc][0][0] = fmaf(p[ky    ][1], w.y, acc[oc][0][0]);
                    acc[oc][0][1] = fmaf(p[ky    ][3], w.y, acc[oc][0][1]);
                    acc[oc][1][0] = fmaf(p[ky + 2][1], w.y, acc[oc][1][0]);
                    acc[oc][1][1] = fmaf(p[ky + 2][3], w.y, acc[oc][1][1]);
                    acc[oc][0][0] = fmaf(p[ky    ][2], w.z, acc[oc][0][0]);
                    acc[oc][0][1] = fmaf(p[ky    ][4], w.z, acc[oc][0][1]);
                    acc[oc][1][0] = fmaf(p[ky + 2][2], w.z, acc[oc][1][0]);
                    acc[oc][1][1] = fmaf(p[ky + 2][4], w.z, acc[oc][1][1]);
                }
            }
        }
        __syncthreads();
    }

    // Epilogue: max-pool -> +bias -> sigmoid; score partial
    const int oy = byy * 4 + py, ox = bx * 8 + px;
    float* fb = feat + (size_t)b * C2_ * 16 * 16;
    float lsum = 0.f;
#pragma unroll
    for (int oc = 0; oc < 8; oc++) {
        int c = grp * 8 + oc;
        float m = fmaxf(fmaxf(acc[oc][0][0], acc[oc][0][1]),
                        fmaxf(acc[oc][1][0], acc[oc][1][1]));
        float v = m + sm[BI2_OFF + c];
        float sig = 1.f / (1.f + __expf(-v));
        fb[c * 256 + oy * 16 + ox] = sig;
        lsum += sig;
    }
#pragma unroll
    for (int o = 16; o > 0; o >>= 1) lsum += __shfl_down_sync(0xffffffffu, lsum, o);
    if ((t & 31) == 0) sm[RED2_OFF + (t >> 5)] = lsum;
    __syncthreads();
    if (t < 8) {
        lsum = sm[RED2_OFF + t];
#pragma unroll
        for (int o = 4; o > 0; o >>= 1) lsum += __shfl_down_sync(0xffu, lsum, o);
        if (t == 0) g_part[b * 8 + byy * 2 + bx] = lsum;
    }
}

// ---------------------------------------------------------------------------
// Kernel 3: final score: sum 8 partials per image -> scores + detected
// ---------------------------------------------------------------------------
__global__ void __launch_bounds__(256) score_final(
    float* __restrict__ scores, float* __restrict__ detected)
{
    int b = blockIdx.x * 256 + threadIdx.x;
    if (b >= B_) return;
    const float4* p = (const float4*)(g_part + b * 8);
    float4 u = p[0], w = p[1];
    float s = ((u.x + u.y) + (u.z + u.w)) + ((w.x + w.y) + (w.z + w.w));
    float sc = s * (1.f / 16384.f);
    scores[b]   = sc;
    detected[b] = (sc >= 0.55f) ? 1.f : 0.f;
}

// ---------------------------------------------------------------------------
extern "C" void kernel_launch(void* const* d_in, const int* in_sizes, int n_in,
                              void* d_out, int out_size)
{
    const float* crops = (const float*)d_in[0];
    const float* w1  = (const float*)d_in[1];
    const float* b1  = (const float*)d_in[2];
    const float* g1  = (const float*)d_in[3];
    const float* be1 = (const float*)d_in[4];
    const float* m1  = (const float*)d_in[5];
    const float* v1  = (const float*)d_in[6];
    const float* w2  = (const float*)d_in[7];
    const float* b2  = (const float*)d_in[8];
    const float* g2  = (const float*)d_in[9];
    const float* be2 = (const float*)d_in[10];
    const float* m2  = (const float*)d_in[11];
    const float* v2  = (const float*)d_in[12];

    float* out      = (float*)d_out;
    float* feat     = out;                                   // 512*64*16*16
    float* scores   = out + (size_t)B_ * C2_ * 16 * 16;      // +512
    float* detected = scores + B_;                           // +512

    static int smem_set = 0;
    if (!smem_set) {
        cudaFuncSetAttribute(conv2_fused,
                             cudaFuncAttributeMaxDynamicSharedMemorySize,
                             CONV2_SMEM_BYTES);
        smem_set = 1;
    }

    conv2_prep<<<72, 256>>>(w2, g2, v2);
    conv1_fused<<<dim3(2, 4, B_), 256>>>(crops, w1, b1, g1, be1, m1, v1);
    conv2_fused<<<dim3(2, 4, B_), 256, CONV2_SMEM_BYTES>>>(b2, g2, be2, m2, v2, feat);
    score_final<<<2, 256>>>(scores, detected);
}

// round 16
// speedup vs baseline: 1.0013x; 1.0013x over previous
#include <cuda_runtime.h>
#include <cstdint>

#define B_    512
#define HW_   128
#define C1_   32
#define C2_   64

// Padded intermediate h: [512][32][66][68], zero border. Valid data [1..64][1..64].
#define HP_R   66
#define HP_C   68
#define HP_CH  (HP_R * HP_C)          // 4488
__device__ float g_h[(size_t)B_ * C1_ * HP_CH];   // ~294 MB

// Pre-packed conv2 weights: [cc][oc][cil][ky][4], pre-scaled by BN scale.
__device__ float g_w2p[8 * 3072];
// Per-image partial sums from conv2 blocks: [b][4]
__device__ float g_part[B_ * 4];

// ---- cp.async helpers -----------------------------------------------------
__device__ __forceinline__ uint32_t sptr(const void* p) {
    return (uint32_t)__cvta_generic_to_shared(p);
}
__device__ __forceinline__ void cpa16(uint32_t dst, const void* src) {
    asm volatile("cp.async.cg.shared.global [%0], [%1], 16;" :: "r"(dst), "l"(src));
}
__device__ __forceinline__ void cpa4(uint32_t dst, const void* src) {
    asm volatile("cp.async.ca.shared.global [%0], [%1], 4;" :: "r"(dst), "l"(src));
}
__device__ __forceinline__ void cpa_commit() {
    asm volatile("cp.async.commit_group;" ::: "memory");
}
template <int N>
__device__ __forceinline__ void cpa_wait() {
    asm volatile("cp.async.wait_group %0;" :: "n"(N) : "memory");
}

// ---------------------------------------------------------------------------
// Kernel 0: pre-pack conv2 weights (18432 items)
// ---------------------------------------------------------------------------
__global__ void conv2_prep(const float* __restrict__ w2,
                           const float* __restrict__ g2,
                           const float* __restrict__ v2)
{
    int i = blockIdx.x * 256 + threadIdx.x;
    if (i >= 8 * C2_ * 36) return;
    int cc  = i / (C2_ * 36);
    int rem = i % (C2_ * 36);
    int oc  = rem / 36;
    int k2  = rem % 36;
    int cil = k2 / 9, k = k2 % 9;
    int ky = k / 3, kx = k % 3;
    float inv = g2[oc] * rsqrtf(v2[oc] + 1e-5f);
    g_w2p[cc * 3072 + oc * 48 + cil * 12 + ky * 4 + kx] =
        w2[oc * (C1_ * 9) + (cc * 4 + cil) * 9 + k] * inv;
}

// ---------------------------------------------------------------------------
// Kernel 1: Conv(3->32, k3, s1, p1) + BN + ReLU + MaxPool2  (R12 form, proven)
// Grid (2, 4, 512), 256 thr. Two horizontal pooled pixels per thread.
// ---------------------------------------------------------------------------
__global__ void __launch_bounds__(256) conv1_fused(
    const float* __restrict__ crops,
    const float* __restrict__ w1, const float* __restrict__ b1,
    const float* __restrict__ g1, const float* __restrict__ be1,
    const float* __restrict__ m1, const float* __restrict__ v1)
{
    __shared__ float s_in[3][34][68];
    __shared__ __align__(16) float s_w[C1_ * 36];
    __shared__ float s_bias[C1_];

    const int b   = blockIdx.z;
    const int cx0 = blockIdx.x * 64;
    const int cy0 = blockIdx.y * 32;
    const int t   = threadIdx.x;

    if (t < C1_) {
        float inv = g1[t] * rsqrtf(v1[t] + 1e-5f);
        s_bias[t] = be1[t] + (b1[t] - m1[t]) * inv;
    }
    for (int i = t; i < C1_ * 27; i += 256) {
        int oc = i / 27, k = i % 27;
        int ci = k / 9, ky = (k % 9) / 3, kx = k % 3;
        float inv = g1[oc] * rsqrtf(v1[oc] + 1e-5f);
        s_w[oc * 36 + ci * 12 + ky * 4 + kx] = w1[i] * inv;
    }

    const float* cb = crops + (size_t)b * 3 * HW_ * HW_;
    for (int i = t; i < 3 * 34 * 66; i += 256) {
        int ci = i / (34 * 66);
        int rem = i % (34 * 66);
        int r = rem / 66, c = rem % 66;
        int gr = cy0 - 1 + r, gc = cx0 - 1 + c;
        float v = 0.f;
        if (gr >= 0 && gr < HW_ && gc >= 0 && gc < HW_)
            v = cb[ci * HW_ * HW_ + gr * HW_ + gc];
        s_in[ci][r][c] = v;
    }
    __syncthreads();

    const int q  = t & 15;
    const int py = t >> 4;

    float p[3][4][6];
#pragma unroll
    for (int ci = 0; ci < 3; ci++)
#pragma unroll
        for (int r = 0; r < 4; r++) {
            const float* row = &s_in[ci][2 * py + r][4 * q];
            float4 v4 = *(const float4*)row;
            float2 v2 = *(const float2*)(row + 4);
            p[ci][r][0] = v4.x; p[ci][r][1] = v4.y; p[ci][r][2] = v4.z;
            p[ci][r][3] = v4.w; p[ci][r][4] = v2.x; p[ci][r][5] = v2.y;
        }

    const int oy = blockIdx.y * 16 + py;
    const int ox = blockIdx.x * 32 + 2 * q;
    float* hp = g_h + (size_t)b * C1_ * HP_CH + (oy + 1) * HP_C + (ox + 1);
    const float* wp = s_w;

    for (int oc = 0; oc < C1_; oc++, hp += HP_CH, wp += 36) {
        float a00 = 0.f, a01 = 0.f, a10 = 0.f, a11 = 0.f;
        float c00 = 0.f, c01 = 0.f, c10 = 0.f, c11 = 0.f;
        const float4* w4 = (const float4*)wp;
#pragma unroll
        for (int ci = 0; ci < 3; ci++)
#pragma unroll
            for (int ky = 0; ky < 3; ky++) {
                float4 w = w4[ci * 3 + ky];
                const float* r0 = p[ci][ky];
                const float* r1 = p[ci][ky + 1];
                a00 = fmaf(r0[0], w.x, a00);  a01 = fmaf(r0[1], w.x, a01);
                a10 = fmaf(r1[0], w.x, a10);  a11 = fmaf(r1[1], w.x, a11);
                c00 = fmaf(r0[2], w.x, c00);  c01 = fmaf(r0[3], w.x, c01);
                c10 = fmaf(r1[2], w.x, c10);  c11 = fmaf(r1[3], w.x, c11);
                a00 = fmaf(r0[1], w.y, a00);  a01 = fmaf(r0[2], w.y, a01);
                a10 = fmaf(r1[1], w.y, a10);  a11 = fmaf(r1[2], w.y, a11);
                c00 = fmaf(r0[3], w.y, c00);  c01 = fmaf(r0[4], w.y, c01);
                c10 = fmaf(r1[3], w.y, c10);  c11 = fmaf(r1[4], w.y, c11);
                a00 = fmaf(r0[2], w.z, a00);  a01 = fmaf(r0[3], w.z, a01);
                a10 = fmaf(r1[2], w.z, a10);  a11 = fmaf(r1[3], w.z, a11);
                c00 = fmaf(r0[4], w.z, c00);  c01 = fmaf(r0[5], w.z, c01);
                c10 = fmaf(r1[4], w.z, c10);  c11 = fmaf(r1[5], w.z, c11);
            }
        float bi = s_bias[oc];
        float mA = fmaxf(fmaxf(a00, a01), fmaxf(a10, a11)) + bi;
        float mB = fmaxf(fmaxf(c00, c01), fmaxf(c10, c11)) + bi;
        hp[0] = fmaxf(mA, 0.f);
        hp[1] = fmaxf(mB, 0.f);
    }
}

// ---------------------------------------------------------------------------
// Kernel 2: Conv(32->64, s2) + BN + Sigmoid + MaxPool2.
// 3-stage cp.async pipeline: ONE barrier per chunk, prefetch depth 2.
// Stage p at float offset p*STG_F: in 4752 | w 3072. 3 stages = 91.7 KB.
// ---------------------------------------------------------------------------
#define STG_F        7824
#define STG_W_OFF    4752
#define BI_OFF       (3 * STG_F)           // 23472
#define RED_OFF      (BI_OFF + 64)         // 23536
#define CONV2_SMEM_BYTES  ((3 * STG_F + 64 + 8) * 4)

__global__ void __launch_bounds__(256) conv2_fused(
    const float* __restrict__ b2, const float* __restrict__ g2,
    const float* __restrict__ be2, const float* __restrict__ m2,
    const float* __restrict__ v2,
    float* __restrict__ feat)
{
    extern __shared__ __align__(16) float sm[];

    const int b  = blockIdx.z;
    const int bx = blockIdx.x, by = blockIdx.y;
    const int t  = threadIdx.x;

    if (t < C2_) {
        float inv = g2[t] * rsqrtf(v2[t] + 1e-5f);
        sm[BI_OFF + t] = be2[t] + (b2[t] - m2[t]) * inv;
    }

    const float* hp = g_h + (size_t)b * C1_ * HP_CH + (32 * by) * HP_C + (32 * bx);
    const uint32_t sm_u32 = sptr(sm);

    // ---- precompute fill offsets (loop-invariant across chunks) ----
    // input: 1188 items = 4ch x 33r x (8x float4 + 1x float); 5 per thread max
    int  in_src[5];      // float offset from hp (chunk-0 base)
    int  in_dst[5];      // byte offset within stage
    bool in_wide[5], in_valid[5];
#pragma unroll
    for (int k = 0; k < 5; k++) {
        int i = t + 256 * k;
        in_valid[k] = (i < 1188);
        int ii = in_valid[k] ? i : 0;
        int ch  = ii / 297;
        int rem = ii - ch * 297;
        int r   = rem / 9;
        int s   = rem - r * 9;
        bool w  = (s < 8);
        in_wide[k] = w;
        in_src[k]  = ch * HP_CH + r * HP_C + (w ? 4 * s : 32);
        in_dst[k]  = ((ch * 33 + r) * 36) * 4 + (w ? 16 * s : 128);
    }

    // ---- issue async copies for chunk cc into stage p (no waiting) ----
    auto issue = [&](int cc, int p) {
        const uint32_t base = sm_u32 + (uint32_t)(p * STG_F) * 4u;
        const float* srcb = hp + cc * (4 * HP_CH);
#pragma unroll
        for (int k = 0; k < 5; k++) {
            if (in_valid[k]) {
                if (in_wide[k]) cpa16(base + in_dst[k], srcb + in_src[k]);
                else            cpa4(base + in_dst[k], srcb + in_src[k]);
            }
        }
        const float4* ws = (const float4*)(g_w2p + cc * 3072);
        const uint32_t wb = base + STG_W_OFF * 4u;
#pragma unroll
        for (int k = 0; k < 3; k++)
            cpa16(wb + 16u * (t + 256 * k), ws + t + 256 * k);
        cpa_commit();
    };

    const int pix = t & 63, grp = t >> 6;      // grp 0..3 -> 16 oc each
    const int px = pix & 7, py = pix >> 3;

    float acc[16][2][2];
#pragma unroll
    for (int i = 0; i < 16; i++) {
        acc[i][0][0] = 0.f; acc[i][0][1] = 0.f;
        acc[i][1][0] = 0.f; acc[i][1][1] = 0.f;
    }

    issue(0, 0);
    issue(1, 1);

    for (int cc = 0; cc < 8; cc++) {
        if (cc < 7) cpa_wait<1>();      // group cc complete (in-order retire)
        else        cpa_wait<0>();
        __syncthreads();                // data visible; everyone past compute(cc-1)

        const int cur = cc % 3;
        const float* sin = sm + cur * STG_F;
        const float* sw  = sin + STG_W_OFF;

#pragma unroll
        for (int cil = 0; cil < 4; cil++) {
            const float* row = sin + (cil * 33 + 4 * py) * 36 + 4 * px;
            float p[5][5];
#pragma unroll
            for (int r = 0; r < 5; r++) {
                float4 v4 = *(const float4*)(row + r * 36);
                p[r][0] = v4.x; p[r][1] = v4.y; p[r][2] = v4.z; p[r][3] = v4.w;
                p[r][4] = row[r * 36 + 4];
            }

#pragma unroll
            for (int oc = 0; oc < 16; oc++) {
                const float4* w4 = (const float4*)(sw + (grp * 16 + oc) * 48 + cil * 12);
#pragma unroll
                for (int ky = 0; ky < 3; ky++) {
                    float4 w = w4[ky];
                    acc[oc][0][0] = fmaf(p[ky    ][0], w.x, acc[oc][0][0]);
                    acc[oc][0][1] = fmaf(p[ky    ][2], w.x, acc[oc][0][1]);
                    acc[oc][1][0] = fmaf(p[ky + 2][0], w.x, acc[oc][1][0]);
                    acc[oc][1][1] = fmaf(p[ky + 2][2], w.x, acc[oc][1][1]);
                    acc[oc][0][0] = fmaf(p[ky    ][1], w.y, acc[oc][0][0]);
                    acc[oc][0][1] = fmaf(p[ky    ][3], w.y, acc[oc][0][1]);
                    acc[oc][1][0] = fmaf(p[ky + 2][1], w.y, acc[oc][1][0]);
                    acc[oc][1][1] = fmaf(p[ky + 2][3], w.y, acc[oc][1][1]);
                    acc[oc][0][0] = fmaf(p[ky    ][2], w.z, acc[oc][0][0]);
                    acc[oc][0][1] = fmaf(p[ky    ][4], w.z, acc[oc][0][1]);
                    acc[oc][1][0] = fmaf(p[ky + 2][2], w.z, acc[oc][1][0]);
                    acc[oc][1][1] = fmaf(p[ky + 2][4], w.z, acc[oc][1][1]);
                }
            }
        }

        // Refill buffer (cc+2)%3 == (cc-1)%3: its readers (compute cc-1)
        // all passed this iteration's barrier already -> safe without a
        // second barrier.
        if (cc < 6) issue(cc + 2, (cc + 2) % 3);
    }

    // Epilogue: max-pool -> +bias -> sigmoid; accumulate score partial
    const int oy = by * 8 + py, ox = bx * 8 + px;
    float* fb = feat + (size_t)b * C2_ * 16 * 16;
    float lsum = 0.f;
#pragma unroll
    for (int oc = 0; oc < 16; oc++) {
        int c = grp * 16 + oc;
        float m = fmaxf(fmaxf(acc[oc][0][0], acc[oc][0][1]),
                        fmaxf(acc[oc][1][0], acc[oc][1][1]));
        float v = m + sm[BI_OFF + c];
        float sig = 1.f / (1.f + __expf(-v));
        fb[c * 256 + oy * 16 + ox] = sig;
        lsum += sig;
    }
#pragma unroll
    for (int o = 16; o > 0; o >>= 1) lsum += __shfl_down_sync(0xffffffffu, lsum, o);
    if ((t & 31) == 0) sm[RED_OFF + (t >> 5)] = lsum;
    __syncthreads();
    if (t < 8) {
        lsum = sm[RED_OFF + t];
#pragma unroll
        for (int o = 4; o > 0; o >>= 1) lsum += __shfl_down_sync(0xffu, lsum, o);
        if (t == 0) g_part[b * 4 + by * 2 + bx] = lsum;
    }
}

// ---------------------------------------------------------------------------
// Kernel 3: final score: sum 4 partials per image -> scores + detected
// ---------------------------------------------------------------------------
__global__ void __launch_bounds__(256) score_final(
    float* __restrict__ scores, float* __restrict__ detected)
{
    int b = blockIdx.x * 256 + threadIdx.x;
    if (b >= B_) return;
    const float* p = g_part + b * 4;
    float s = (p[0] + p[1]) + (p[2] + p[3]);
    float sc = s * (1.f / 16384.f);
    scores[b]   = sc;
    detected[b] = (sc >= 0.55f) ? 1.f : 0.f;
}

// ---------------------------------------------------------------------------
extern "C" void kernel_launch(void* const* d_in, const int* in_sizes, int n_in,
                              void* d_out, int out_size)
{
    const float* crops = (const float*)d_in[0];
    const float* w1  = (const float*)d_in[1];
    const float* b1  = (const float*)d_in[2];
    const float* g1  = (const float*)d_in[3];
    const float* be1 = (const float*)d_in[4];
    const float* m1  = (const float*)d_in[5];
    const float* v1  = (const float*)d_in[6];
    const float* w2  = (const float*)d_in[7];
    const float* b2  = (const float*)d_in[8];
    const float* g2  = (const float*)d_in[9];
    const float* be2 = (const float*)d_in[10];
    const float* m2  = (const float*)d_in[11];
    const float* v2  = (const float*)d_in[12];

    float* out      = (float*)d_out;
    float* feat     = out;                                   // 512*64*16*16
    float* scores   = out + (size_t)B_ * C2_ * 16 * 16;      // +512
    float* detected = scores + B_;                           // +512

    static int smem_set = 0;
    if (!smem_set) {
        cudaFuncSetAttribute(conv2_fused,
                             cudaFuncAttributeMaxDynamicSharedMemorySize,
                             CONV2_SMEM_BYTES);
        smem_set = 1;
    }

    conv2_prep<<<72, 256>>>(w2, g2, v2);
    conv1_fused<<<dim3(2, 4, B_), 256>>>(crops, w1, b1, g1, be1, m1, v1);
    conv2_fused<<<dim3(2, 2, B_), 256, CONV2_SMEM_BYTES>>>(b2, g2, be2, m2, v2, feat);
    score_final<<<2, 256>>>(scores, detected);
}

// round 17
// speedup vs baseline: 1.0061x; 1.0048x over previous
#include <cuda_runtime.h>
#include <cstdint>

#define B_    512
#define HW_   128
#define C1_   32
#define C2_   64

// Padded intermediate h: [512][32][66][68], zero border. Valid data [1..64][1..64].
// Values are pre-rounded to tf32 (consumed only by tensor-core conv2).
#define HP_R   66
#define HP_C   68
#define HP_CH  (HP_R * HP_C)          // 4488
__device__ float g_h[(size_t)B_ * C1_ * HP_CH];   // ~294 MB

// Transposed conv2 weights for tensor cores: [pos(9)][ci(32), stride 66][oc(64)],
// pre-scaled by BN scale, pre-rounded to tf32.
__device__ float g_w2t[9 * 2112];     // 19008 floats
// Per-image score sums
__device__ float g_part[B_];

// ---- cp.async helpers -----------------------------------------------------
__device__ __forceinline__ uint32_t sptr(const void* p) {
    return (uint32_t)__cvta_generic_to_shared(p);
}
__device__ __forceinline__ void cpa16(uint32_t dst, const void* src) {
    asm volatile("cp.async.cg.shared.global [%0], [%1], 16;" :: "r"(dst), "l"(src));
}
__device__ __forceinline__ void cpa_commit() {
    asm volatile("cp.async.commit_group;" ::: "memory");
}
template <int N>
__device__ __forceinline__ void cpa_wait() {
    asm volatile("cp.async.wait_group %0;" :: "n"(N) : "memory");
}

__device__ __forceinline__ uint32_t to_tf32(float f) {
    uint32_t u; asm("cvt.rna.tf32.f32 %0, %1;" : "=r"(u) : "f"(f)); return u;
}

// ---------------------------------------------------------------------------
// Kernel 0: transpose + prescale + tf32-round conv2 weights
// ---------------------------------------------------------------------------
__global__ void conv2_prep_tc(const float* __restrict__ w2,
                              const float* __restrict__ g2,
                              const float* __restrict__ v2)
{
    int i = blockIdx.x * 256 + threadIdx.x;
    if (i >= 9 * C1_ * C2_) return;
    int pos = i / (C1_ * C2_);
    int rem = i % (C1_ * C2_);
    int ci  = rem / C2_;
    int oc  = rem % C2_;
    float inv = g2[oc] * rsqrtf(v2[oc] + 1e-5f);
    float w = w2[oc * (C1_ * 9) + ci * 9 + pos] * inv;
    g_w2t[pos * 2112 + ci * 66 + oc] = __uint_as_float(to_tf32(w));
}

// ---------------------------------------------------------------------------
// Kernel 1: Conv(3->32, k3, s1, p1) + BN + ReLU + MaxPool2  (R12 form)
// Output pre-rounded to tf32 for the tensor-core consumer.
// ---------------------------------------------------------------------------
__global__ void __launch_bounds__(256) conv1_fused(
    const float* __restrict__ crops,
    const float* __restrict__ w1, const float* __restrict__ b1,
    const float* __restrict__ g1, const float* __restrict__ be1,
    const float* __restrict__ m1, const float* __restrict__ v1)
{
    __shared__ float s_in[3][34][68];
    __shared__ __align__(16) float s_w[C1_ * 36];
    __shared__ float s_bias[C1_];

    const int b   = blockIdx.z;
    const int cx0 = blockIdx.x * 64;
    const int cy0 = blockIdx.y * 32;
    const int t   = threadIdx.x;

    if (t < C1_) {
        float inv = g1[t] * rsqrtf(v1[t] + 1e-5f);
        s_bias[t] = be1[t] + (b1[t] - m1[t]) * inv;
    }
    for (int i = t; i < C1_ * 27; i += 256) {
        int oc = i / 27, k = i % 27;
        int ci = k / 9, ky = (k % 9) / 3, kx = k % 3;
        float inv = g1[oc] * rsqrtf(v1[oc] + 1e-5f);
        s_w[oc * 36 + ci * 12 + ky * 4 + kx] = w1[i] * inv;
    }

    const float* cb = crops + (size_t)b * 3 * HW_ * HW_;
    for (int i = t; i < 3 * 34 * 66; i += 256) {
        int ci = i / (34 * 66);
        int rem = i % (34 * 66);
        int r = rem / 66, c = rem % 66;
        int gr = cy0 - 1 + r, gc = cx0 - 1 + c;
        float v = 0.f;
        if (gr >= 0 && gr < HW_ && gc >= 0 && gc < HW_)
            v = cb[ci * HW_ * HW_ + gr * HW_ + gc];
        s_in[ci][r][c] = v;
    }
    __syncthreads();

    const int q  = t & 15;
    const int py = t >> 4;

    float p[3][4][6];
#pragma unroll
    for (int ci = 0; ci < 3; ci++)
#pragma unroll
        for (int r = 0; r < 4; r++) {
            const float* row = &s_in[ci][2 * py + r][4 * q];
            float4 v4 = *(const float4*)row;
            float2 v2 = *(const float2*)(row + 4);
            p[ci][r][0] = v4.x; p[ci][r][1] = v4.y; p[ci][r][2] = v4.z;
            p[ci][r][3] = v4.w; p[ci][r][4] = v2.x; p[ci][r][5] = v2.y;
        }

    const int oy = blockIdx.y * 16 + py;
    const int ox = blockIdx.x * 32 + 2 * q;
    float* hp = g_h + (size_t)b * C1_ * HP_CH + (oy + 1) * HP_C + (ox + 1);
    const float* wp = s_w;

    for (int oc = 0; oc < C1_; oc++, hp += HP_CH, wp += 36) {
        float a00 = 0.f, a01 = 0.f, a10 = 0.f, a11 = 0.f;
        float c00 = 0.f, c01 = 0.f, c10 = 0.f, c11 = 0.f;
        const float4* w4 = (const float4*)wp;
#pragma unroll
        for (int ci = 0; ci < 3; ci++)
#pragma unroll
            for (int ky = 0; ky < 3; ky++) {
                float4 w = w4[ci * 3 + ky];
                const float* r0 = p[ci][ky];
                const float* r1 = p[ci][ky + 1];
                a00 = fmaf(r0[0], w.x, a00);  a01 = fmaf(r0[1], w.x, a01);
                a10 = fmaf(r1[0], w.x, a10);  a11 = fmaf(r1[1], w.x, a11);
                c00 = fmaf(r0[2], w.x, c00);  c01 = fmaf(r0[3], w.x, c01);
                c10 = fmaf(r1[2], w.x, c10);  c11 = fmaf(r1[3], w.x, c11);
                a00 = fmaf(r0[1], w.y, a00);  a01 = fmaf(r0[2], w.y, a01);
                a10 = fmaf(r1[1], w.y, a10);  a11 = fmaf(r1[2], w.y, a11);
                c00 = fmaf(r0[3], w.y, c00);  c01 = fmaf(r0[4], w.y, c01);
                c10 = fmaf(r1[3], w.y, c10);  c11 = fmaf(r1[4], w.y, c11);
                a00 = fmaf(r0[2], w.z, a00);  a01 = fmaf(r0[3], w.z, a01);
                a10 = fmaf(r1[2], w.z, a10);  a11 = fmaf(r1[3], w.z, a11);
                c00 = fmaf(r0[4], w.z, c00);  c01 = fmaf(r0[5], w.z, c01);
                c10 = fmaf(r1[4], w.z, c10);  c11 = fmaf(r1[5], w.z, c11);
            }
        float bi = s_bias[oc];
        float mA = fmaxf(fmaxf(fmaxf(a00, a01), fmaxf(a10, a11)) + bi, 0.f);
        float mB = fmaxf(fmaxf(fmaxf(c00, c01), fmaxf(c10, c11)) + bi, 0.f);
        hp[0] = __uint_as_float(to_tf32(mA));
        hp[1] = __uint_as_float(to_tf32(mB));
    }
}

// ---------------------------------------------------------------------------
// Kernel 2: Conv(32->64, s2) + BN + Sigmoid + MaxPool2 via tf32 mma.sync.
// One block per image, 256 thr (8 warps). Per M-tile (4 conv rows = 128 px):
// warp w owns m16 stripe (conv row w>>1, cols (w&1)*16 ..+16).
// K = 4 chunks of 8 ci x 9 taps; A from smem input tile, B from smem weights.
// Epilogue: D -> Y smem -> maxpool + bias + sigmoid -> feat + score partial.
// smem (floats): W[0,19008) | IN 2x4896 [19008,28800) | Y 128x66 [28800,37248)
//                bias @37248, red @37312.  Total 149280 B.
// ---------------------------------------------------------------------------
#define W_OFF    0
#define IN_OFF   19008
#define STG_SZ   4896
#define Y_OFF    28800
#define BI_OFF   37248
#define RED_OFF  37312
#define TC_SMEM_BYTES  (37320 * 4)

#define MMA_TF32(d, a0, a1, a2, a3, b0, b1) \
    asm volatile( \
        "mma.sync.aligned.m16n8k8.row.col.f32.tf32.tf32.f32 " \
        "{%0,%1,%2,%3}, {%4,%5,%6,%7}, {%8,%9}, {%0,%1,%2,%3};" \
        : "+f"(d[0]), "+f"(d[1]), "+f"(d[2]), "+f"(d[3]) \
        : "r"(a0), "r"(a1), "r"(a2), "r"(a3), "r"(b0), "r"(b1))

__global__ void __launch_bounds__(256) conv2_tc(
    const float* __restrict__ b2, const float* __restrict__ g2,
    const float* __restrict__ be2, const float* __restrict__ m2,
    const float* __restrict__ v2,
    float* __restrict__ feat)
{
    extern __shared__ __align__(16) float sm[];

    const int b    = blockIdx.x;
    const int t    = threadIdx.x;
    const int wid  = t >> 5;
    const int lane = t & 31;
    const int g8   = lane >> 2;       // groupID 0..7
    const int tid4 = lane & 3;        // threadID in group

    if (t < C2_) {
        float inv = g2[t] * rsqrtf(v2[t] + 1e-5f);
        sm[BI_OFF + t] = be2[t] + (b2[t] - m2[t]) * inv;
    }

    const float* hb = g_h + (size_t)b * C1_ * HP_CH;
    const uint32_t sm_u32 = sptr(sm);

    // ---- weight fill: 19008 floats = 4752 float4 (one-time) ----
    {
        const float4* ws = (const float4*)g_w2t;
        const uint32_t wb = sm_u32 + W_OFF * 4u;
        for (int j = 0; j < 19; j++) {
            int i = t + 256 * j;
            if (i < 4752) cpa16(wb + 16u * i, ws + i);
        }
        cpa_commit();
    }

    // ---- input fill offsets (constant across chunks) ----
    // per chunk: 8 ci x 612 contiguous floats (rows 8mt..8mt+8) = 1224 float4
    int  fsrc[5], fdst[5];            // float offset / byte offset
    bool fval[5];
#pragma unroll
    for (int k = 0; k < 5; k++) {
        int i = t + 256 * k;
        fval[k] = (i < 1224);
        int ii = fval[k] ? i : 0;
        int ci_l = ii / 153;          // float4 count per ci = 153
        int rem  = ii - ci_l * 153;
        fsrc[k] = ci_l * HP_CH + rem * 4;
        fdst[k] = (ci_l * 612 + rem * 4) * 4;
    }

    auto issue = [&](int klin) {      // klin = mt*4 + cc, stage = klin&1
        int mt = klin >> 2, cc = klin & 3;
        const float* srcb = hb + cc * 8 * HP_CH + mt * (8 * HP_C);
        const uint32_t base = sm_u32 + (uint32_t)(IN_OFF + (klin & 1) * STG_SZ) * 4u;
#pragma unroll
        for (int k = 0; k < 5; k++)
            if (fval[k]) cpa16(base + fdst[k], srcb + fsrc[k]);
        cpa_commit();
    };

    issue(0);

    // warp geometry
    const int rloc = wid >> 1;                 // conv row within M-tile (0..3)
    const int c0   = (wid & 1) * 16;           // conv col base of m16 stripe

    float d[8][4];
#pragma unroll
    for (int nt = 0; nt < 8; nt++) {
        d[nt][0] = 0.f; d[nt][1] = 0.f; d[nt][2] = 0.f; d[nt][3] = 0.f;
    }

    float lsum = 0.f;
    float* fb = feat + (size_t)b * C2_ * 256;

    for (int k = 0; k < 32; k++) {
        if (k < 31) { issue(k + 1); cpa_wait<1>(); }
        else        { cpa_wait<0>(); }
        __syncthreads();

        const int cc = k & 3;
        const uint32_t* stg = (const uint32_t*)(sm + IN_OFF + (k & 1) * STG_SZ);
        const uint32_t* wsm = (const uint32_t*)(sm + W_OFF);

#pragma unroll
        for (int pos = 0; pos < 9; pos++) {
            const int ky = pos / 3, kx = pos % 3;
            const int lr = 2 * rloc + ky;
            const int colb = 2 * (c0 + g8) + kx;
            const int abase = tid4 * 612 + lr * 68 + colb;
            uint32_t a0 = stg[abase];
            uint32_t a1 = stg[abase + 16];
            uint32_t a2 = stg[abase + 4 * 612];
            uint32_t a3 = stg[abase + 4 * 612 + 16];

            const uint32_t* wp = wsm + pos * 2112 + (cc * 8 + tid4) * 66 + g8;
#pragma unroll
            for (int nt = 0; nt < 8; nt++) {
                uint32_t b0 = wp[nt * 8];
                uint32_t b1 = wp[nt * 8 + 264];   // ci + 4
                MMA_TF32(d[nt], a0, a1, a2, a3, b0, b1);
            }
        }

        if ((k & 3) == 3) {
            // ---- epilogue for mt = k>>2 ----
            const int mt = k >> 2;
            float* Yp = sm + Y_OFF;
            const int row = wid * 16 + g8;
#pragma unroll
            for (int nt = 0; nt < 8; nt++) {
                int col = nt * 8 + 2 * tid4;
                *(float2*)&Yp[row * 66 + col]       = make_float2(d[nt][0], d[nt][1]);
                *(float2*)&Yp[(row + 8) * 66 + col] = make_float2(d[nt][2], d[nt][3]);
                d[nt][0] = 0.f; d[nt][1] = 0.f; d[nt][2] = 0.f; d[nt][3] = 0.f;
            }
            __syncthreads();

            const int grpo = t >> 5;            // 8 oc-groups
            const int pp = t & 31;
            const int pr = pp >> 4, pc = pp & 15;
            const int p00 = (2 * pr) * 32 + 2 * pc;
            const float* y0 = &Yp[p00 * 66];
            const float* y1 = &Yp[(p00 + 1) * 66];
            const float* y2 = &Yp[(p00 + 32) * 66];
            const float* y3 = &Yp[(p00 + 33) * 66];
            const int orow = (2 * mt + pr) * 16 + pc;
#pragma unroll
            for (int j = 0; j < 8; j++) {
                int oc = grpo * 8 + j;
                float m = fmaxf(fmaxf(y0[oc], y1[oc]), fmaxf(y2[oc], y3[oc]));
                float v = m + sm[BI_OFF + oc];
                float sig = 1.f / (1.f + __expf(-v));
                fb[oc * 256 + orow] = sig;
                lsum += sig;
            }
        }
        __syncthreads();
    }

    // final score reduce (one value per image)
#pragma unroll
    for (int o = 16; o > 0; o >>= 1) lsum += __shfl_down_sync(0xffffffffu, lsum, o);
    if (lane == 0) sm[RED_OFF + wid] = lsum;
    __syncthreads();
    if (t == 0) {
        float s = 0.f;
#pragma unroll
        for (int i = 0; i < 8; i++) s += sm[RED_OFF + i];
        g_part[b] = s;
    }
}

// ---------------------------------------------------------------------------
// Kernel 3: final score -> scores + detected
// ---------------------------------------------------------------------------
__global__ void __launch_bounds__(256) score_final(
    float* __restrict__ scores, float* __restrict__ detected)
{
    int b = blockIdx.x * 256 + threadIdx.x;
    if (b >= B_) return;
    float sc = g_part[b] * (1.f / 16384.f);
    scores[b]   = sc;
    detected[b] = (sc >= 0.55f) ? 1.f : 0.f;
}

// ---------------------------------------------------------------------------
extern "C" void kernel_launch(void* const* d_in, const int* in_sizes, int n_in,
                              void* d_out, int out_size)
{
    const float* crops = (const float*)d_in[0];
    const float* w1  = (const float*)d_in[1];
    const float* b1  = (const float*)d_in[2];
    const float* g1  = (const float*)d_in[3];
    const float* be1 = (const float*)d_in[4];
    const float* m1  = (const float*)d_in[5];
    const float* v1  = (const float*)d_in[6];
    const float* w2  = (const float*)d_in[7];
    const float* b2  = (const float*)d_in[8];
    const float* g2  = (const float*)d_in[9];
    const float* be2 = (const float*)d_in[10];
    const float* m2  = (const float*)d_in[11];
    const float* v2  = (const float*)d_in[12];

    float* out      = (float*)d_out;
    float* feat     = out;                                   // 512*64*16*16
    float* scores   = out + (size_t)B_ * C2_ * 16 * 16;      // +512
    float* detected = scores + B_;                           // +512

    static int smem_set = 0;
    if (!smem_set) {
        cudaFuncSetAttribute(conv2_tc,
                             cudaFuncAttributeMaxDynamicSharedMemorySize,
                             TC_SMEM_BYTES);
        smem_set = 1;
    }

    conv2_prep_tc<<<72, 256>>>(w2, g2, v2);
    conv1_fused<<<dim3(2, 4, B_), 256>>>(crops, w1, b1, g1, be1, m1, v1);
    conv2_tc<<<B_, 256, TC_SMEM_BYTES>>>(b2, g2, be2, m2, v2, feat);
    score_final<<<2, 256>>>(scores, detected);
}